// round 1
// baseline (speedup 1.0000x reference)
#include <cuda_runtime.h>
#include <math.h>

// Shapes are fixed by the problem instance.
#define D        3
#define NF       8
#define FEAT     48     // D*2*NF
#define BL       128
#define OUT      4
#define KNBR     8
#define RPB      128    // rows per block
#define TPB      256
#define SA       132    // padded activation row stride (floats)

__device__ __forceinline__ float gelu_exact(float x) {
    return 0.5f * x * (1.0f + erff(x * 0.70710678118654752f));
}

// Load nf4 float4's from global weight matrix into smem (all 256 threads).
__device__ __forceinline__ void load_w(const float* __restrict__ g, float* s,
                                       int nf4, int tid) {
    const float4* __restrict__ g4 = (const float4*)g;
    float4* s4 = (float4*)s;
    for (int i = tid; i < nf4; i += TPB) s4[i] = __ldg(&g4[i]);
}

// One MLP layer: Bs[128][BL] = gelu(As[128][KDIM] @ Ws[KDIM][BL] + bias)
// Thread (tm,tn) computes rows {tm*4..tm*4+3} U {64+tm*4..64+tm*4+3},
// cols {tn*8..tn*8+7}. The 4+4 row split keeps the two tm-groups of a warp
// on different smem banks (4*SA = 528 -> bank offset 16): conflict-free LDS.
template<int KDIM>
__device__ __forceinline__ void layer(const float* __restrict__ As,
                                      const float* __restrict__ Ws,
                                      const float* __restrict__ bias,
                                      float* __restrict__ Bs,
                                      int tm, int tn) {
    const int c0 = tn * 8;
    const int rb0 = tm * 4;
    const int rb1 = tm * 4 + 64;

    float acc[8][8];
    #pragma unroll
    for (int rr = 0; rr < 8; rr++)
        #pragma unroll
        for (int cc = 0; cc < 8; cc++) acc[rr][cc] = 0.0f;

    #pragma unroll 4
    for (int i = 0; i < KDIM; i++) {
        float a[8];
        #pragma unroll
        for (int rr = 0; rr < 4; rr++) a[rr]     = As[(rb0 + rr) * SA + i];
        #pragma unroll
        for (int rr = 0; rr < 4; rr++) a[rr + 4] = As[(rb1 + rr) * SA + i];

        float4 w0 = *(const float4*)(Ws + i * BL + c0);
        float4 w1 = *(const float4*)(Ws + i * BL + c0 + 4);
        float b[8] = {w0.x, w0.y, w0.z, w0.w, w1.x, w1.y, w1.z, w1.w};

        #pragma unroll
        for (int rr = 0; rr < 8; rr++)
            #pragma unroll
            for (int cc = 0; cc < 8; cc++)
                acc[rr][cc] = fmaf(a[rr], b[cc], acc[rr][cc]);
    }

    float bs[8];
    #pragma unroll
    for (int cc = 0; cc < 8; cc++) bs[cc] = __ldg(bias + c0 + cc);

    #pragma unroll
    for (int rr = 0; rr < 8; rr++) {
        const int r = (rr < 4) ? (rb0 + rr) : (rb1 + rr - 4);
        float4 o0, o1;
        o0.x = gelu_exact(acc[rr][0] + bs[0]);
        o0.y = gelu_exact(acc[rr][1] + bs[1]);
        o0.z = gelu_exact(acc[rr][2] + bs[2]);
        o0.w = gelu_exact(acc[rr][3] + bs[3]);
        o1.x = gelu_exact(acc[rr][4] + bs[4]);
        o1.y = gelu_exact(acc[rr][5] + bs[5]);
        o1.z = gelu_exact(acc[rr][6] + bs[6]);
        o1.w = gelu_exact(acc[rr][7] + bs[7]);
        *(float4*)(Bs + r * SA + c0)     = o0;
        *(float4*)(Bs + r * SA + c0 + 4) = o1;
    }
}

__global__ void __launch_bounds__(TPB, 1)
domino_kernel(const float* __restrict__ q,      // (M,3)
              const float* __restrict__ pts,    // (N,3)
              const float* __restrict__ freqs,  // (NF)
              const float* __restrict__ W1, const float* __restrict__ b1,
              const float* __restrict__ W2, const float* __restrict__ b2,
              const float* __restrict__ W3, const float* __restrict__ b3,
              const float* __restrict__ W4, const float* __restrict__ b4,
              const float* __restrict__ W5, const float* __restrict__ b5,
              const int*   __restrict__ mapping, // (M*K)
              float* __restrict__ out,           // (M,4)
              int nrows) {
    extern __shared__ float smem[];
    float* As = smem;
    float* Bs = smem + RPB * SA;
    float* Ws = smem + 2 * RPB * SA;

    const int tid = threadIdx.x;
    const int tm = tid >> 4;
    const int tn = tid & 15;

    // ---- Stage 0: Fourier features into As (threads 0..127); W1 staged by all.
    load_w(W1, Ws, FEAT * BL / 4, tid);

    if (tid < RPB) {
        const int g = blockIdx.x * RPB + tid;
        float rx = 0.f, ry = 0.f, rz = 0.f;
        if (g < nrows) {
            const int m = g >> 3;                 // K = 8
            const int idx = mapping[g];
            rx = __ldg(pts + idx * 3 + 0) - __ldg(q + m * 3 + 0);
            ry = __ldg(pts + idx * 3 + 1) - __ldg(q + m * 3 + 1);
            rz = __ldg(pts + idx * 3 + 2) - __ldg(q + m * 3 + 2);
        }
        float* fr = As + tid * SA;
        #pragma unroll
        for (int f = 0; f < NF; f++) {
            const float fq = __ldg(freqs + f);
            float s0, c0, s1, c1, s2, c2;
            sincosf(rx * fq, &s0, &c0);
            sincosf(ry * fq, &s1, &c1);
            sincosf(rz * fq, &s2, &c2);
            fr[f * 3 + 0] = s0;  fr[f * 3 + 1] = s1;  fr[f * 3 + 2] = s2;
            fr[24 + f * 3 + 0] = c0;  fr[24 + f * 3 + 1] = c1;  fr[24 + f * 3 + 2] = c2;
        }
    }
    __syncthreads();

    // ---- Layer 1: As(feat) -> Bs
    layer<FEAT>(As, Ws, b1, Bs, tm, tn);
    __syncthreads();
    load_w(W2, Ws, BL * BL / 4, tid);
    __syncthreads();

    // ---- Layer 2: Bs -> As
    layer<BL>(Bs, Ws, b2, As, tm, tn);
    __syncthreads();
    load_w(W3, Ws, BL * BL / 4, tid);
    __syncthreads();

    // ---- Layer 3: As -> Bs
    layer<BL>(As, Ws, b3, Bs, tm, tn);
    __syncthreads();
    load_w(W4, Ws, BL * BL / 4, tid);
    __syncthreads();

    // ---- Layer 4: Bs -> As
    layer<BL>(Bs, Ws, b4, As, tm, tn);
    __syncthreads();
    load_w(W5, Ws, BL * OUT / 4, tid);   // W5: 128x4 floats = 128 float4
    __syncthreads();

    // ---- Layer 5 + mean over K=8 neighbors (threads 0..127, one per row)
    if (tid < RPB) {
        const int r = tid;
        float a0 = 0.f, a1 = 0.f, a2 = 0.f, a3 = 0.f;
        const float4* __restrict__ W54 = (const float4*)Ws;
        #pragma unroll 8
        for (int i = 0; i < BL; i++) {
            const float a = As[r * SA + i];
            const float4 w = W54[i];
            a0 = fmaf(a, w.x, a0);
            a1 = fmaf(a, w.y, a1);
            a2 = fmaf(a, w.z, a2);
            a3 = fmaf(a, w.w, a3);
        }
        // Butterfly sum over the 8 neighbors (8 consecutive lanes per query).
        #pragma unroll
        for (int off = 4; off > 0; off >>= 1) {
            a0 += __shfl_xor_sync(0xffffffffu, a0, off);
            a1 += __shfl_xor_sync(0xffffffffu, a1, off);
            a2 += __shfl_xor_sync(0xffffffffu, a2, off);
            a3 += __shfl_xor_sync(0xffffffffu, a3, off);
        }
        const int g = blockIdx.x * RPB + r;
        if ((r & 7) == 0 && g < nrows) {
            const int m = g >> 3;
            out[m * 4 + 0] = a0 * 0.125f + __ldg(b5 + 0);
            out[m * 4 + 1] = a1 * 0.125f + __ldg(b5 + 1);
            out[m * 4 + 2] = a2 * 0.125f + __ldg(b5 + 2);
            out[m * 4 + 3] = a3 * 0.125f + __ldg(b5 + 3);
        }
    }
}

extern "C" void kernel_launch(void* const* d_in, const int* in_sizes, int n_in,
                              void* d_out, int out_size) {
    const float* q       = (const float*)d_in[0];
    const float* pts     = (const float*)d_in[1];
    const float* freqs   = (const float*)d_in[2];
    const float* W1      = (const float*)d_in[3];
    const float* b1      = (const float*)d_in[4];
    const float* W2      = (const float*)d_in[5];
    const float* b2      = (const float*)d_in[6];
    const float* W3      = (const float*)d_in[7];
    const float* b3      = (const float*)d_in[8];
    const float* W4      = (const float*)d_in[9];
    const float* b4      = (const float*)d_in[10];
    const float* W5      = (const float*)d_in[11];
    const float* b5      = (const float*)d_in[12];
    const int*   mapping = (const int*)d_in[13];

    const int nrows = in_sizes[13];            // B*M*K row count
    const int blocks = (nrows + RPB - 1) / RPB;

    const size_t smem_bytes = (size_t)(2 * RPB * SA + BL * BL) * sizeof(float); // 200704 B
    cudaFuncSetAttribute(domino_kernel,
                         cudaFuncAttributeMaxDynamicSharedMemorySize,
                         (int)smem_bytes);

    domino_kernel<<<blocks, TPB, smem_bytes>>>(
        q, pts, freqs, W1, b1, W2, b2, W3, b3, W4, b4, W5, b5,
        mapping, (float*)d_out, nrows);
}

// round 8
// speedup vs baseline: 1.5208x; 1.5208x over previous
#include <cuda_runtime.h>
#include <cuda_bf16.h>
#include <stdint.h>
#include <math.h>

// Problem shape constants
#define NF   8
#define FEAT 48
#define BL   128
#define KNBR 8
#define RPB  128            // rows per block (= 16 queries x 8 neighbors)
#define TPB  256

// smem layout: bf16 matrices, row stride 136 elems (272 B = 68 words == 4 mod 8
// -> conflict-free ldmatrix row addressing)
#define SK   136
#define SKB  272
#define ABYTES (RPB * SKB)          // 34816
#define OFF_AH 0
#define OFF_AL (ABYTES)
#define OFF_WH (2 * ABYTES)
#define OFF_WL (3 * ABYTES)
#define SMEM_BYTES (4 * ABYTES)     // 139264

__device__ __forceinline__ float gelu_exact(float x) {
    return 0.5f * x * (1.0f + erff(x * 0.70710678118654752f));
}

__device__ __forceinline__ uint32_t cvta_smem(const void* p) {
    uint32_t a;
    asm volatile("{.reg .u64 t; cvta.to.shared.u64 t, %1; cvt.u32.u64 %0, t;}"
                 : "=r"(a) : "l"(p));
    return a;
}

__device__ __forceinline__ void ldsm_x4(uint32_t addr, uint32_t* r) {
    asm volatile("ldmatrix.sync.aligned.m8n8.x4.shared.b16 {%0,%1,%2,%3}, [%4];"
                 : "=r"(r[0]), "=r"(r[1]), "=r"(r[2]), "=r"(r[3]) : "r"(addr));
}
__device__ __forceinline__ void ldsm_x4t(uint32_t addr, uint32_t* r) {
    asm volatile("ldmatrix.sync.aligned.m8n8.x4.trans.shared.b16 {%0,%1,%2,%3}, [%4];"
                 : "=r"(r[0]), "=r"(r[1]), "=r"(r[2]), "=r"(r[3]) : "r"(addr));
}
__device__ __forceinline__ void mma_bf16(float* c, const uint32_t* a,
                                         uint32_t b0, uint32_t b1) {
    asm volatile("mma.sync.aligned.m16n8k16.row.col.f32.bf16.bf16.f32 "
                 "{%0,%1,%2,%3},{%4,%5,%6,%7},{%8,%9},{%0,%1,%2,%3};"
                 : "+f"(c[0]), "+f"(c[1]), "+f"(c[2]), "+f"(c[3])
                 : "r"(a[0]), "r"(a[1]), "r"(a[2]), "r"(a[3]), "r"(b0), "r"(b1));
}

// x -> (hi, lo) bf16 pair; packs two lanes into one 32-bit word (low elem in low bits)
__device__ __forceinline__ void split_pack(float x, float y, uint32_t& hi, uint32_t& lo) {
    __nv_bfloat162 h = __floats2bfloat162_rn(x, y);
    float rx = x - __bfloat162float(h.x);
    float ry = y - __bfloat162float(h.y);
    __nv_bfloat162 l = __floats2bfloat162_rn(rx, ry);
    hi = *reinterpret_cast<uint32_t*>(&h);
    lo = *reinterpret_cast<uint32_t*>(&l);
}

// Warp-level GEMM: acc[2][8][4] += split(A[32 rows x 16*KC]) @ split(W[16*KC x 128])
// Warp covers rows 32*wm..+31, cols 64*wn..+63. 3-term bf16 split per product.
template <int KC>
__device__ __forceinline__ void gemm_warp(uint32_t sAh, uint32_t sAl,
                                          uint32_t sWh, uint32_t sWl,
                                          int wm, int wn, int lane,
                                          float acc[2][8][4]) {
    const int i = lane & 7, j = lane >> 3;
    // A (non-trans): matrix j -> row += (j&1)*8, col += (j>>1)*8
    const uint32_t aoff = (uint32_t)((32 * wm + i + (j & 1) * 8) * SKB + (j >> 1) * 16);
    // B (trans): matrix j -> k-row += (j&1)*8, n-col += (j>>1)*8
    const uint32_t boff = (uint32_t)((i + (j & 1) * 8) * SKB + (64 * wn + (j >> 1) * 8) * 2);

    #pragma unroll
    for (int kc = 0; kc < KC; kc++) {
        uint32_t ah[2][4], al[2][4];
        ldsm_x4(sAh + aoff + kc * 32, ah[0]);
        ldsm_x4(sAh + aoff + 16 * SKB + kc * 32, ah[1]);
        ldsm_x4(sAl + aoff + kc * 32, al[0]);
        ldsm_x4(sAl + aoff + 16 * SKB + kc * 32, al[1]);
        #pragma unroll
        for (int np = 0; np < 4; np++) {
            const uint32_t ba = boff + np * 32 + kc * 16 * SKB;
            uint32_t bh[4], bl[4];
            ldsm_x4t(sWh + ba, bh);
            ldsm_x4t(sWl + ba, bl);
            #pragma unroll
            for (int mt = 0; mt < 2; mt++) {
                mma_bf16(acc[mt][2 * np],     ah[mt], bh[0], bh[1]);
                mma_bf16(acc[mt][2 * np],     al[mt], bh[0], bh[1]);
                mma_bf16(acc[mt][2 * np],     ah[mt], bl[0], bl[1]);
                mma_bf16(acc[mt][2 * np + 1], ah[mt], bh[2], bh[3]);
                mma_bf16(acc[mt][2 * np + 1], al[mt], bh[2], bh[3]);
                mma_bf16(acc[mt][2 * np + 1], ah[mt], bl[2], bl[3]);
            }
        }
    }
}

// bias + exact GELU + hi/lo split, written in place into Ah/Al
__device__ __forceinline__ void epilogue(float acc[2][8][4], const float* __restrict__ bias,
                                         char* smB, int wm, int wn, int lane) {
    const int g = lane >> 2, t = lane & 3;
    #pragma unroll
    for (int mt = 0; mt < 2; mt++) {
        const int r0 = 32 * wm + 16 * mt + g;
        #pragma unroll
        for (int nt = 0; nt < 8; nt++) {
            const int c = 64 * wn + 8 * nt + 2 * t;
            const float bc0 = __ldg(bias + c), bc1 = __ldg(bias + c + 1);
            float y00 = gelu_exact(acc[mt][nt][0] + bc0);
            float y01 = gelu_exact(acc[mt][nt][1] + bc1);
            float y10 = gelu_exact(acc[mt][nt][2] + bc0);
            float y11 = gelu_exact(acc[mt][nt][3] + bc1);
            uint32_t h0, l0, h1, l1;
            split_pack(y00, y01, h0, l0);
            split_pack(y10, y11, h1, l1);
            *(uint32_t*)(smB + OFF_AH + (size_t)r0 * SKB + c * 2)       = h0;
            *(uint32_t*)(smB + OFF_AL + (size_t)r0 * SKB + c * 2)       = l0;
            *(uint32_t*)(smB + OFF_AH + (size_t)(r0 + 8) * SKB + c * 2) = h1;
            *(uint32_t*)(smB + OFF_AL + (size_t)(r0 + 8) * SKB + c * 2) = l1;
        }
    }
}

// global fp32 W[kdim][128] -> smem bf16 hi/lo, row-major, stride SK
__device__ __forceinline__ void load_w_split(const float* __restrict__ Wg, int kdim,
                                             char* smB, int tid) {
    const float4* __restrict__ g4 = (const float4*)Wg;
    const int total = kdim * 32;  // 32 float4 per 128-wide row
    for (int idx = tid; idx < total; idx += TPB) {
        const int k = idx >> 5, n4 = (idx & 31) << 2;
        const float4 w = __ldg(g4 + idx);
        uint32_t h0, l0, h1, l1;
        split_pack(w.x, w.y, h0, l0);
        split_pack(w.z, w.w, h1, l1);
        *(uint2*)(smB + OFF_WH + (size_t)k * SKB + n4 * 2) = make_uint2(h0, h1);
        *(uint2*)(smB + OFF_WL + (size_t)k * SKB + n4 * 2) = make_uint2(l0, l1);
    }
}

__device__ __forceinline__ void zero_acc(float acc[2][8][4]) {
    #pragma unroll
    for (int a = 0; a < 2; a++)
        #pragma unroll
        for (int b = 0; b < 8; b++)
            #pragma unroll
            for (int c = 0; c < 4; c++) acc[a][b][c] = 0.0f;
}

__global__ void __launch_bounds__(TPB, 1)
domino_tc_kernel(const float* __restrict__ q, const float* __restrict__ pts,
                 const float* __restrict__ freqs,
                 const float* __restrict__ W1, const float* __restrict__ b1,
                 const float* __restrict__ W2, const float* __restrict__ b2,
                 const float* __restrict__ W3, const float* __restrict__ b3,
                 const float* __restrict__ W4, const float* __restrict__ b4,
                 const float* __restrict__ W5, const float* __restrict__ b5,
                 const int* __restrict__ mapping, float* __restrict__ out,
                 int nrows) {
    extern __shared__ char smB[];
    const uint32_t sbase = cvta_smem(smB);
    const uint32_t sAh = sbase + OFF_AH, sAl = sbase + OFF_AL;
    const uint32_t sWh = sbase + OFF_WH, sWl = sbase + OFF_WL;

    const int tid = threadIdx.x, lane = tid & 31, wid = tid >> 5;
    const int wm = wid >> 1, wn = wid & 1;

    // ---- Stage 0: W1 into smem (split) + Fourier features (2 threads / row)
    load_w_split(W1, FEAT, smB, tid);
    {
        const int row = tid >> 1, half = tid & 1;
        const int g = blockIdx.x * RPB + row;
        float rx = 0.f, ry = 0.f, rz = 0.f;
        if (g < nrows) {
            const int m = g >> 3;
            const int idx = mapping[g];
            rx = __ldg(pts + idx * 3 + 0) - __ldg(q + m * 3 + 0);
            ry = __ldg(pts + idx * 3 + 1) - __ldg(q + m * 3 + 1);
            rz = __ldg(pts + idx * 3 + 2) - __ldg(q + m * 3 + 2);
        }
        char* rowH = smB + OFF_AH + (size_t)row * SKB;
        char* rowL = smB + OFF_AL + (size_t)row * SKB;
        #pragma unroll
        for (int f = 0; f < 4; f++) {
            const int fi = half * 4 + f;
            const float fq = __ldg(freqs + fi);
            float sv[3], cv[3];
            sincosf(rx * fq, &sv[0], &cv[0]);
            sincosf(ry * fq, &sv[1], &cv[1]);
            sincosf(rz * fq, &sv[2], &cv[2]);
            #pragma unroll
            for (int d = 0; d < 3; d++) {
                const int cs = fi * 3 + d, cc = 24 + fi * 3 + d;
                __nv_bfloat16 sh = __float2bfloat16(sv[d]);
                __nv_bfloat16 ch = __float2bfloat16(cv[d]);
                *(__nv_bfloat16*)(rowH + cs * 2) = sh;
                *(__nv_bfloat16*)(rowL + cs * 2) = __float2bfloat16(sv[d] - __bfloat162float(sh));
                *(__nv_bfloat16*)(rowH + cc * 2) = ch;
                *(__nv_bfloat16*)(rowL + cc * 2) = __float2bfloat16(cv[d] - __bfloat162float(ch));
            }
        }
    }
    __syncthreads();

    float acc[2][8][4];

    // ---- Layer 1 (K = 48)
    zero_acc(acc);
    gemm_warp<3>(sAh, sAl, sWh, sWl, wm, wn, lane, acc);
    __syncthreads();
    epilogue(acc, b1, smB, wm, wn, lane);
    load_w_split(W2, BL, smB, tid);
    __syncthreads();

    // ---- Layer 2
    zero_acc(acc);
    gemm_warp<8>(sAh, sAl, sWh, sWl, wm, wn, lane, acc);
    __syncthreads();
    epilogue(acc, b2, smB, wm, wn, lane);
    load_w_split(W3, BL, smB, tid);
    __syncthreads();

    // ---- Layer 3
    zero_acc(acc);
    gemm_warp<8>(sAh, sAl, sWh, sWl, wm, wn, lane, acc);
    __syncthreads();
    epilogue(acc, b3, smB, wm, wn, lane);
    load_w_split(W4, BL, smB, tid);
    __syncthreads();

    // ---- Layer 4
    zero_acc(acc);
    gemm_warp<8>(sAh, sAl, sWh, sWl, wm, wn, lane, acc);
    __syncthreads();
    epilogue(acc, b4, smB, wm, wn, lane);
    __syncthreads();

    // ---- Layer 5 (128 -> 4) + mean over K = 8 neighbors
    if (tid < RPB) {
        const int r = tid;
        float a0 = 0.f, a1 = 0.f, a2 = 0.f, a3 = 0.f;
        const uint32_t* ah = (const uint32_t*)(smB + OFF_AH + (size_t)r * SKB);
        const uint32_t* al = (const uint32_t*)(smB + OFF_AL + (size_t)r * SKB);
        const float4* __restrict__ W54 = (const float4*)W5;
        #pragma unroll 8
        for (int k2 = 0; k2 < 64; k2++) {
            const uint32_t hp = ah[k2], lp = al[k2];
            const __nv_bfloat162 hb = *reinterpret_cast<const __nv_bfloat162*>(&hp);
            const __nv_bfloat162 lb = *reinterpret_cast<const __nv_bfloat162*>(&lp);
            const float x0 = __bfloat162float(hb.x) + __bfloat162float(lb.x);
            const float x1 = __bfloat162float(hb.y) + __bfloat162float(lb.y);
            const float4 w0 = __ldg(W54 + 2 * k2);
            const float4 w1 = __ldg(W54 + 2 * k2 + 1);
            a0 = fmaf(x0, w0.x, a0); a1 = fmaf(x0, w0.y, a1);
            a2 = fmaf(x0, w0.z, a2); a3 = fmaf(x0, w0.w, a3);
            a0 = fmaf(x1, w1.x, a0); a1 = fmaf(x1, w1.y, a1);
            a2 = fmaf(x1, w1.z, a2); a3 = fmaf(x1, w1.w, a3);
        }
        #pragma unroll
        for (int off = 4; off > 0; off >>= 1) {
            a0 += __shfl_xor_sync(0xffffffffu, a0, off);
            a1 += __shfl_xor_sync(0xffffffffu, a1, off);
            a2 += __shfl_xor_sync(0xffffffffu, a2, off);
            a3 += __shfl_xor_sync(0xffffffffu, a3, off);
        }
        const int g = blockIdx.x * RPB + r;
        if ((r & 7) == 0 && g < nrows) {
            const int m = g >> 3;
            out[m * 4 + 0] = a0 * 0.125f + __ldg(b5 + 0);
            out[m * 4 + 1] = a1 * 0.125f + __ldg(b5 + 1);
            out[m * 4 + 2] = a2 * 0.125f + __ldg(b5 + 2);
            out[m * 4 + 3] = a3 * 0.125f + __ldg(b5 + 3);
        }
    }
}

extern "C" void kernel_launch(void* const* d_in, const int* in_sizes, int n_in,
                              void* d_out, int out_size) {
    const float* q       = (const float*)d_in[0];
    const float* pts     = (const float*)d_in[1];
    const float* freqs   = (const float*)d_in[2];
    const float* W1      = (const float*)d_in[3];
    const float* b1      = (const float*)d_in[4];
    const float* W2      = (const float*)d_in[5];
    const float* b2      = (const float*)d_in[6];
    const float* W3      = (const float*)d_in[7];
    const float* b3      = (const float*)d_in[8];
    const float* W4      = (const float*)d_in[9];
    const float* b4      = (const float*)d_in[10];
    const float* W5      = (const float*)d_in[11];
    const float* b5      = (const float*)d_in[12];
    const int*   mapping = (const int*)d_in[13];

    const int nrows = in_sizes[13];
    const int blocks = (nrows + RPB - 1) / RPB;

    cudaFuncSetAttribute(domino_tc_kernel,
                         cudaFuncAttributeMaxDynamicSharedMemorySize, SMEM_BYTES);

    domino_tc_kernel<<<blocks, TPB, SMEM_BYTES>>>(
        q, pts, freqs, W1, b1, W2, b2, W3, b3, W4, b4, W5, b5,
        mapping, (float*)d_out, nrows);
}